// round 2
// baseline (speedup 1.0000x reference)
#include <cuda_runtime.h>

#define BB 32
#define NN 2000
#define DD 5
#define GRP 5
#define TOPK 110

// Scratch (allocation-free rule: __device__ globals)
__device__ float g_Q[BB * NN * DD];   // pre-scaled by log2e/sqrt(5)
__device__ float g_K[BB * NN * DD];
__device__ float g_diag[BB * NN];

__device__ __forceinline__ float ex2(float x) {
    float y;
    asm("ex2.approx.ftz.f32 %0, %1;" : "=f"(y) : "f"(x));
    return y;
}

// ---------------------------------------------------------------------------
// Kernel A: input projection + Q/K projection for every (b, n) point.
// ---------------------------------------------------------------------------
__global__ void proj_kernel(const float* __restrict__ in_mat,
                            const float* __restrict__ Wi, const float* __restrict__ bi,
                            const float* __restrict__ Wq, const float* __restrict__ bq,
                            const float* __restrict__ Wk, const float* __restrict__ bk) {
    int idx = blockIdx.x * blockDim.x + threadIdx.x;
    if (idx >= BB * NN) return;
    const float* p = in_mat + idx * 3;
    float i0 = p[0], i1 = p[1], i2 = p[2];

    float x[DD];
#pragma unroll
    for (int j = 0; j < DD; j++)
        x[j] = fmaf(i0, Wi[j], fmaf(i1, Wi[DD + j], fmaf(i2, Wi[2 * DD + j], bi[j])));

    // Fold log2(e)/sqrt(5) into Q so scores are directly in log2 domain.
    const float qscale = 1.4426950408889634f / 2.2360679774997896f;
#pragma unroll
    for (int j = 0; j < DD; j++) {
        float q = bq[j], k = bk[j];
#pragma unroll
        for (int d = 0; d < DD; d++) {
            q = fmaf(x[d], Wq[d * DD + j], q);
            k = fmaf(x[d], Wk[d * DD + j], k);
        }
        g_Q[idx * DD + j] = q * qscale;
        g_K[idx * DD + j] = k;
    }
}

// ---------------------------------------------------------------------------
// Kernel B: softmax-diagonal.  grid = (ceil(N/256), B), block = 256.
// K[b] staged in smem as SoA (float4 + float) -> 2 LDS per score.
// All threads sweep m in lockstep -> smem broadcasts (conflict-free).
// ---------------------------------------------------------------------------
__global__ void diag_kernel() {
    __shared__ float4 Ks4[NN];   // k0..k3   (32 KB)
    __shared__ float  Ks1[NN];   // k4       ( 8 KB)

    int b = blockIdx.y;
    int n = blockIdx.x * blockDim.x + threadIdx.x;

    const float* Kb = g_K + b * NN * DD;
    for (int m = threadIdx.x; m < NN; m += blockDim.x) {
        float k0 = Kb[m * DD + 0], k1 = Kb[m * DD + 1];
        float k2 = Kb[m * DD + 2], k3 = Kb[m * DD + 3];
        Ks4[m] = make_float4(k0, k1, k2, k3);
        Ks1[m] = Kb[m * DD + 4];
    }
    __syncthreads();
    if (n >= NN) return;

    const float* qp = g_Q + (b * NN + n) * DD;
    float q0 = qp[0], q1 = qp[1], q2 = qp[2], q3 = qp[3], q4 = qp[4];

    float mx = -1e30f, sum = 0.0f;
#pragma unroll 4
    for (int m = 0; m < NN; m++) {
        float4 kv = Ks4[m];
        float v = fmaf(q4, Ks1[m],
                  fmaf(q3, kv.w, fmaf(q2, kv.z, fmaf(q1, kv.y, q0 * kv.x))));
        if (v <= mx) {
            sum += ex2(v - mx);
        } else {
            sum = fmaf(sum, ex2(mx - v), 1.0f);   // rescale + exp(0)=1 for new max
            mx = v;
        }
    }
    float4 kn = Ks4[n];
    float vn = fmaf(q4, Ks1[n],
               fmaf(q3, kn.w, fmaf(q2, kn.z, fmaf(q1, kn.y, q0 * kn.x))));
    g_diag[b * NN + n] = ex2(vn - mx) / sum;
}

// ---------------------------------------------------------------------------
// Kernel C: group argmax -> centroid -> distances -> stable top-110 gather.
// One block per batch, 256 threads.
// ---------------------------------------------------------------------------
__global__ void select_kernel(const float* __restrict__ in_mat,
                              float* __restrict__ out) {
    __shared__ float dist[NN];
    __shared__ float bestV[256];
    __shared__ int   bestI[256];
    __shared__ float cen[3];

    int b = blockIdx.x;
    int t = threadIdx.x;
    const float* db = g_diag + b * NN;

    // group sums + per-thread argmax (first-max wins within a thread: strict >)
    float bv = -1e30f;
    int bidx = 0x7fffffff;
    for (int g = t; g < NN / GRP; g += blockDim.x) {
        const float* d5 = db + g * GRP;
        float s = d5[0] + d5[1] + d5[2] + d5[3] + d5[4];
        if (s > bv) { bv = s; bidx = g; }
    }
    bestV[t] = bv;
    bestI[t] = bidx;
    __syncthreads();

    if (t == 0) {
        float v = bestV[0]; int gi = bestI[0];
        for (int i = 1; i < 256; i++) {
            // jax argmax tie-break: lowest index
            if (bestV[i] > v || (bestV[i] == v && bestI[i] < gi)) {
                v = bestV[i]; gi = bestI[i];
            }
        }
        const float* gp = in_mat + (b * NN + gi * GRP) * 3;
        float cx = 0.f, cy = 0.f, cz = 0.f;
        for (int p = 0; p < GRP; p++) {
            cx += gp[p * 3 + 0];
            cy += gp[p * 3 + 1];
            cz += gp[p * 3 + 2];
        }
        cen[0] = cx * 0.2f; cen[1] = cy * 0.2f; cen[2] = cz * 0.2f;
    }
    __syncthreads();

    float cx = cen[0], cy = cen[1], cz = cen[2];
    for (int n = t; n < NN; n += blockDim.x) {
        const float* p = in_mat + (b * NN + n) * 3;
        float dx = p[0] - cx, dy = p[1] - cy, dz = p[2] - cz;
        dist[n] = sqrtf(fmaf(dx, dx, fmaf(dy, dy, dz * dz)));
    }
    __syncthreads();

    // rank counting == jax.lax.top_k(-dist) stable ordering
    for (int n = t; n < NN; n += blockDim.x) {
        float dn = dist[n];
        int r = 0;
#pragma unroll 4
        for (int m = 0; m < NN; m++) {
            float dm = dist[m];                 // broadcast read (lockstep m)
            r += (dm < dn) || (dm == dn && m < n);
        }
        if (r < TOPK) {
            const float* p = in_mat + (b * NN + n) * 3;
            float* o = out + (b * TOPK + r) * 3;
            o[0] = p[0]; o[1] = p[1]; o[2] = p[2];
        }
    }
}

// ---------------------------------------------------------------------------
extern "C" void kernel_launch(void* const* d_in, const int* in_sizes, int n_in,
                              void* d_out, int out_size) {
    const float* in_mat = (const float*)d_in[0];
    const float* Wi = (const float*)d_in[1];
    const float* bi = (const float*)d_in[2];
    const float* Wq = (const float*)d_in[3];
    const float* bq = (const float*)d_in[4];
    const float* Wk = (const float*)d_in[5];
    const float* bk = (const float*)d_in[6];
    // d_in[7..10] (Wv, bv, Wo, bo) are dead code w.r.t. the output.
    float* out = (float*)d_out;

    proj_kernel<<<(BB * NN + 255) / 256, 256>>>(in_mat, Wi, bi, Wq, bq, Wk, bk);

    dim3 gB((NN + 255) / 256, BB);
    diag_kernel<<<gB, 256>>>();

    select_kernel<<<BB, 256>>>(in_mat, out);
}

// round 4
// speedup vs baseline: 4.0303x; 4.0303x over previous
#include <cuda_runtime.h>

#define BB 32
#define NN 2000
#define NP (NN / 2)          // 1000 pairs
#define DD 5
#define GRP 5
#define TOPK 110

typedef unsigned long long u64;

// ---- device scratch (allocation-free rule) --------------------------------
__device__ float g_Q[BB * NN * DD];          // pre-scaled by log2e/sqrt(5)
__device__ ulonglong2 g_KA[BB * NP];         // (k0[2p],k0[2p+1] | k1[2p],k1[2p+1])
__device__ ulonglong2 g_KB[BB * NP];         // (k2 pair | k3 pair)
__device__ u64        g_KC[BB * NP];         // (k4 pair)
__device__ float g_diag[BB * NN];

// ---- PTX helpers ----------------------------------------------------------
__device__ __forceinline__ float ex2(float x) {
    float y;
    asm("ex2.approx.ftz.f32 %0, %1;" : "=f"(y) : "f"(x));
    return y;
}
__device__ __forceinline__ u64 pk(float lo, float hi) {
    u64 r;
    asm("mov.b64 %0, {%1, %2};" : "=l"(r) : "f"(lo), "f"(hi));
    return r;
}
__device__ __forceinline__ float2 up(u64 v) {
    float2 r;
    asm("mov.b64 {%0, %1}, %2;" : "=f"(r.x), "=f"(r.y) : "l"(v));
    return r;
}
__device__ __forceinline__ u64 fma2(u64 a, u64 b, u64 c) {
    u64 d;
    asm("fma.rn.f32x2 %0, %1, %2, %3;" : "=l"(d) : "l"(a), "l"(b), "l"(c));
    return d;
}

// ---------------------------------------------------------------------------
// Kernel A: input proj + Q/K proj; K written in paired layout for kernel B.
// ---------------------------------------------------------------------------
__global__ void proj_kernel(const float* __restrict__ in_mat,
                            const float* __restrict__ Wi, const float* __restrict__ bi,
                            const float* __restrict__ Wq, const float* __restrict__ bq,
                            const float* __restrict__ Wk, const float* __restrict__ bk) {
    int idx = blockIdx.x * blockDim.x + threadIdx.x;
    if (idx >= BB * NN) return;
    const float* p = in_mat + idx * 3;
    float i0 = p[0], i1 = p[1], i2 = p[2];

    float x[DD];
#pragma unroll
    for (int j = 0; j < DD; j++)
        x[j] = fmaf(i0, Wi[j], fmaf(i1, Wi[DD + j], fmaf(i2, Wi[2 * DD + j], bi[j])));

    const float qscale = 1.4426950408889634f / 2.2360679774997896f; // log2e/sqrt(5)
    float q[DD], k[DD];
#pragma unroll
    for (int j = 0; j < DD; j++) {
        float qq = bq[j], kk = bk[j];
#pragma unroll
        for (int d = 0; d < DD; d++) {
            qq = fmaf(x[d], Wq[d * DD + j], qq);
            kk = fmaf(x[d], Wk[d * DD + j], kk);
        }
        q[j] = qq * qscale;
        k[j] = kk;
    }

#pragma unroll
    for (int j = 0; j < DD; j++) g_Q[idx * DD + j] = q[j];

    int b = idx / NN, n = idx % NN;
    int pg = b * NP + (n >> 1), h = n & 1;
    float* A = (float*)&g_KA[pg];
    float* Bp = (float*)&g_KB[pg];
    float* C = (float*)&g_KC[pg];
    A[h]     = k[0];
    A[2 + h] = k[1];
    Bp[h]     = k[2];
    Bp[2 + h] = k[3];
    C[h]     = k[4];
}

// ---------------------------------------------------------------------------
// Kernel B: softmax diagonal, branchless, packed f32x2, analytic shift.
// grid = (8, B), block = 256.
// ---------------------------------------------------------------------------
__global__ void diag_kernel() {
    __shared__ ulonglong2 sA[NP];   // 16 KB
    __shared__ ulonglong2 sB[NP];   // 16 KB
    __shared__ u64        sC[NP];   //  8 KB
    __shared__ float red[8];

    int b = blockIdx.y;
    int t = threadIdx.x;
    int n = blockIdx.x * blockDim.x + t;

    const ulonglong2* gA = g_KA + b * NP;
    const ulonglong2* gB = g_KB + b * NP;
    const u64*        gC = g_KC + b * NP;

    // stage K + compute max ||k||^2
    float bmax = 0.0f;
    for (int p = t; p < NP; p += 256) {
        ulonglong2 a = gA[p];
        ulonglong2 bb = gB[p];
        u64 c = gC[p];
        sA[p] = a; sB[p] = bb; sC[p] = c;
        float2 a0 = up(a.x), a1 = up(a.y), b0 = up(bb.x), b1 = up(bb.y), c0 = up(c);
        float ne = fmaf(a0.x, a0.x, fmaf(a1.x, a1.x,
                   fmaf(b0.x, b0.x, fmaf(b1.x, b1.x, c0.x * c0.x))));
        float no = fmaf(a0.y, a0.y, fmaf(a1.y, a1.y,
                   fmaf(b0.y, b0.y, fmaf(b1.y, b1.y, c0.y * c0.y))));
        bmax = fmaxf(bmax, fmaxf(ne, no));
    }
#pragma unroll
    for (int o = 16; o; o >>= 1)
        bmax = fmaxf(bmax, __shfl_xor_sync(0xffffffffu, bmax, o));
    if ((t & 31) == 0) red[t >> 5] = bmax;
    __syncthreads();

    if (n >= NN) return;

    float maxn2 = red[0];
#pragma unroll
    for (int i = 1; i < 8; i++) maxn2 = fmaxf(maxn2, red[i]);

    const float* qp = g_Q + (b * NN + n) * DD;
    float q0 = qp[0], q1 = qp[1], q2 = qp[2], q3 = qp[3], q4 = qp[4];

    // shift >= max_m q.k  (Cauchy-Schwarz); softmax is shift-invariant.
    float shift = sqrtf(fmaf(q0, q0, fmaf(q1, q1, fmaf(q2, q2, fmaf(q3, q3, q4 * q4)))))
                * sqrtf(maxn2);
    u64 qq0 = pk(q0, q0), qq1 = pk(q1, q1), qq2 = pk(q2, q2),
        qq3 = pk(q3, q3), qq4 = pk(q4, q4);
    u64 ns = pk(-shift, -shift);

    float sa = 0.0f, sb = 0.0f;
#pragma unroll 4
    for (int p = 0; p < NP; p++) {
        ulonglong2 a = sA[p];
        ulonglong2 bb = sB[p];
        u64 c = sC[p];
        u64 v = fma2(qq0, a.x, ns);
        v = fma2(qq1, a.y, v);
        v = fma2(qq2, bb.x, v);
        v = fma2(qq3, bb.y, v);
        v = fma2(qq4, c, v);
        float2 vf = up(v);
        sa += ex2(vf.x);
        sb += ex2(vf.y);
    }

    // diagonal numerator
    int ph = n >> 1, h = n & 1;
    const float* fA = (const float*)&sA[ph];
    const float* fB = (const float*)&sB[ph];
    const float* fC = (const float*)&sC[ph];
    float vn = fmaf(q0, fA[h], fmaf(q1, fA[2 + h],
               fmaf(q2, fB[h], fmaf(q3, fB[2 + h], q4 * fC[h])))) - shift;
    g_diag[b * NN + n] = ex2(vn) / (sa + sb);
}

// ---------------------------------------------------------------------------
// Kernel C: group argmax -> centroid -> stable top-110 via rank counting.
// grid = (8, B), block = 256; block (c,b) ranks n in [c*250, c*250+250).
// ---------------------------------------------------------------------------
__global__ void select_kernel(const float* __restrict__ in_mat,
                              float* __restrict__ out) {
    __shared__ u64 key[NN];          // 16 KB
    __shared__ float redv[8];
    __shared__ int   redi[8];
    __shared__ float cen[3];

    int b = blockIdx.y;
    int t = threadIdx.x;
    const float* db = g_diag + b * NN;

    // group sums + argmax (first-max tie-break, matching jnp.argmax)
    float bv = -1e30f;
    int bi = 1 << 30;
    for (int g = t; g < NN / GRP; g += 256) {
        const float* d5 = db + g * GRP;
        float s = d5[0] + d5[1] + d5[2] + d5[3] + d5[4];
        if (s > bv) { bv = s; bi = g; }
    }
#pragma unroll
    for (int o = 16; o; o >>= 1) {
        float ov = __shfl_xor_sync(0xffffffffu, bv, o);
        int   oi = __shfl_xor_sync(0xffffffffu, bi, o);
        if (ov > bv || (ov == bv && oi < bi)) { bv = ov; bi = oi; }
    }
    if ((t & 31) == 0) { redv[t >> 5] = bv; redi[t >> 5] = bi; }
    __syncthreads();

    if (t == 0) {
        float v = redv[0]; int gi = redi[0];
#pragma unroll
        for (int i = 1; i < 8; i++)
            if (redv[i] > v || (redv[i] == v && redi[i] < gi)) { v = redv[i]; gi = redi[i]; }
        const float* gp = in_mat + (b * NN + gi * GRP) * 3;
        float cx = 0.f, cy = 0.f, cz = 0.f;
#pragma unroll
        for (int p = 0; p < GRP; p++) {
            cx += gp[p * 3 + 0]; cy += gp[p * 3 + 1]; cz += gp[p * 3 + 2];
        }
        cen[0] = cx * 0.2f; cen[1] = cy * 0.2f; cen[2] = cz * 0.2f;
    }
    __syncthreads();

    float cx = cen[0], cy = cen[1], cz = cen[2];
    for (int n = t; n < NN; n += 256) {
        const float* p = in_mat + (b * NN + n) * 3;
        float dx = p[0] - cx, dy = p[1] - cy, dz = p[2] - cz;
        float d = sqrtf(fmaf(dx, dx, fmaf(dy, dy, dz * dz)));
        // d >= 0 -> float bits order == value order; index breaks ties stably
        key[n] = (((u64)__float_as_uint(d)) << 11) | (unsigned)n;
    }
    __syncthreads();

    int n = blockIdx.x * 250 + t;
    if (t < 250 && n < NN) {
        u64 kn = key[n];
        int r = 0;
        const ulonglong2* k2 = (const ulonglong2*)key;
#pragma unroll 4
        for (int m2 = 0; m2 < NP; m2++) {
            ulonglong2 kk = k2[m2];
            r += (int)(kk.x < kn) + (int)(kk.y < kn);
        }
        if (r < TOPK) {
            const float* p = in_mat + (b * NN + n) * 3;
            float* o = out + (b * TOPK + r) * 3;
            o[0] = p[0]; o[1] = p[1]; o[2] = p[2];
        }
    }
}

// ---------------------------------------------------------------------------
extern "C" void kernel_launch(void* const* d_in, const int* in_sizes, int n_in,
                              void* d_out, int out_size) {
    const float* in_mat = (const float*)d_in[0];
    const float* Wi = (const float*)d_in[1];
    const float* bi = (const float*)d_in[2];
    const float* Wq = (const float*)d_in[3];
    const float* bq = (const float*)d_in[4];
    const float* Wk = (const float*)d_in[5];
    const float* bk = (const float*)d_in[6];
    // d_in[7..10] (Wv,bv,Wo,bo) are dead w.r.t. the output.
    float* out = (float*)d_out;

    proj_kernel<<<(BB * NN + 255) / 256, 256>>>(in_mat, Wi, bi, Wq, bq, Wk, bk);
    diag_kernel<<<dim3(8, BB), 256>>>();
    select_kernel<<<dim3(8, BB), 256>>>(in_mat, out);
}

// round 5
// speedup vs baseline: 5.4313x; 1.3476x over previous
#include <cuda_runtime.h>

#define BB 32
#define NN 2000
#define DD 5
#define GRP 5
#define TOPK 110
#define TPB 256
#define NCHUNK 8
#define CHUNK 250

typedef unsigned long long u64;

__device__ float g_diag[BB * NN];
__device__ unsigned int g_cnt[BB];   // monotonic arrival counters (zero-init; each launch adds exactly 8 per batch)

// ---- PTX helpers ----------------------------------------------------------
__device__ __forceinline__ float ex2(float x) {
    float y; asm("ex2.approx.ftz.f32 %0, %1;" : "=f"(y) : "f"(x)); return y;
}
__device__ __forceinline__ u64 pk(float lo, float hi) {
    u64 r; asm("mov.b64 %0, {%1, %2};" : "=l"(r) : "f"(lo), "f"(hi)); return r;
}
__device__ __forceinline__ float2 up(u64 v) {
    float2 r; asm("mov.b64 {%0, %1}, %2;" : "=f"(r.x), "=f"(r.y) : "l"(v)); return r;
}
__device__ __forceinline__ u64 fma2(u64 a, u64 b, u64 c) {
    u64 d; asm("fma.rn.f32x2 %0, %1, %2, %3;" : "=l"(d) : "l"(a), "l"(b), "l"(c)); return d;
}
__device__ __forceinline__ u64 add2(u64 a, u64 b) {
    u64 d; asm("add.rn.f32x2 %0, %1, %2;" : "=l"(d) : "l"(a), "l"(b)); return d;
}

// ---------------------------------------------------------------------------
// Fused kernel. grid = (8, 32), block = 256.
//   smem sbuf layout (40000 B):
//     diag phase : K component j at [j*8000, j*8000+8000): float[2000]
//     select phase (overlay, only the last-arriving block per batch uses it):
//       key  u64[2000]  @ 0      (16000 B)
//       hist int[512]   @ 16000  ( 2048 B)
//       cand u64[2000]  @ 18048  (16000 B)
// ---------------------------------------------------------------------------
__global__ void __launch_bounds__(TPB, 2) fused_kernel(
    const float* __restrict__ in_mat,
    const float* __restrict__ Wi, const float* __restrict__ bi,
    const float* __restrict__ Wq, const float* __restrict__ bq,
    const float* __restrict__ Wk, const float* __restrict__ bk,
    float* __restrict__ out)
{
    __shared__ __align__(16) char sbuf[40000];
    __shared__ float wsm[80];       // 0:Wi(15) 15:bi(5) 20:Wk(25) 45:bk(5) 50:Wq(25) 75:bq(5)
    __shared__ float redf[8];
    __shared__ float redf2[8];
    __shared__ int   redi[8];
    __shared__ float cen[3];
    __shared__ int s_ncand, s_bstar;
    __shared__ float s_dmin, s_dmax;
    __shared__ int s_last;

    const int b = blockIdx.y, c = blockIdx.x, t = threadIdx.x;
    const float* base_in = in_mat + b * NN * 3;

    // ---- stage weights ----
    if (t < 15)      wsm[t] = Wi[t];
    else if (t < 20) wsm[t] = bi[t - 15];
    else if (t < 45) wsm[t] = Wk[t - 20];
    else if (t < 50) wsm[t] = bk[t - 45];
    else if (t < 75) wsm[t] = Wq[t - 50];
    else if (t < 80) wsm[t] = bq[t - 75];
    __syncthreads();

    // ---- phase 1: K[b] for all 2000 points -> smem (SoA), plus max||k||^2 ----
    float bmax = 0.0f;
    for (int p = t; p < NN; p += TPB) {
        float i0 = base_in[p * 3], i1 = base_in[p * 3 + 1], i2 = base_in[p * 3 + 2];
        float x[DD];
#pragma unroll
        for (int j = 0; j < DD; j++)
            x[j] = fmaf(i0, wsm[j], fmaf(i1, wsm[5 + j], fmaf(i2, wsm[10 + j], wsm[15 + j])));
        float n2 = 0.0f;
#pragma unroll
        for (int j = 0; j < DD; j++) {
            float kk = wsm[45 + j];
#pragma unroll
            for (int d = 0; d < DD; d++) kk = fmaf(x[d], wsm[20 + d * 5 + j], kk);
            ((float*)(sbuf + j * 8000))[p] = kk;
            n2 = fmaf(kk, kk, n2);
        }
        bmax = fmaxf(bmax, n2);
    }
#pragma unroll
    for (int o = 16; o; o >>= 1) bmax = fmaxf(bmax, __shfl_xor_sync(0xffffffffu, bmax, o));
    if ((t & 31) == 0) redf[t >> 5] = bmax;
    __syncthreads();
    float maxn2 = redf[0];
#pragma unroll
    for (int i = 1; i < 8; i++) maxn2 = fmaxf(maxn2, redf[i]);

    // ---- phase 2: Q for own n, then branchless diag softmax ----
    const int n = c * CHUNK + t;
    const bool active = (t < CHUNK);
    if (active) {
        float i0 = base_in[n * 3], i1 = base_in[n * 3 + 1], i2 = base_in[n * 3 + 2];
        float x[DD];
#pragma unroll
        for (int j = 0; j < DD; j++)
            x[j] = fmaf(i0, wsm[j], fmaf(i1, wsm[5 + j], fmaf(i2, wsm[10 + j], wsm[15 + j])));
        const float qscale = 1.4426950408889634f / 2.2360679774997896f; // log2e/sqrt(5)
        float q[DD];
#pragma unroll
        for (int j = 0; j < DD; j++) {
            float qq = wsm[75 + j];
#pragma unroll
            for (int d = 0; d < DD; d++) qq = fmaf(x[d], wsm[50 + d * 5 + j], qq);
            q[j] = qq * qscale;
        }
        // shift >= max_m q.k (Cauchy-Schwarz); softmax shift-invariant.
        float shift = sqrtf(fmaf(q[0], q[0], fmaf(q[1], q[1],
                      fmaf(q[2], q[2], fmaf(q[3], q[3], q[4] * q[4]))))) * sqrtf(maxn2);

        u64 qq0 = pk(q[0], q[0]), qq1 = pk(q[1], q[1]), qq2 = pk(q[2], q[2]),
            qq3 = pk(q[3], q[3]), qq4 = pk(q[4], q[4]);
        u64 ns = pk(-shift, -shift);

        const ulonglong2* K0 = (const ulonglong2*)(sbuf);
        const ulonglong2* K1 = (const ulonglong2*)(sbuf + 8000);
        const ulonglong2* K2 = (const ulonglong2*)(sbuf + 16000);
        const ulonglong2* K3 = (const ulonglong2*)(sbuf + 24000);
        const ulonglong2* K4 = (const ulonglong2*)(sbuf + 32000);

        u64 acc0 = 0ull, acc1 = 0ull;   // f32x2 {+0,+0}
#pragma unroll 4
        for (int p = 0; p < NN / 4; p++) {
            ulonglong2 A0 = K0[p], A1 = K1[p], A2 = K2[p], A3 = K3[p], A4 = K4[p];
            u64 v0 = fma2(qq0, A0.x, ns);
            v0 = fma2(qq1, A1.x, v0);
            v0 = fma2(qq2, A2.x, v0);
            v0 = fma2(qq3, A3.x, v0);
            v0 = fma2(qq4, A4.x, v0);
            u64 v1 = fma2(qq0, A0.y, ns);
            v1 = fma2(qq1, A1.y, v1);
            v1 = fma2(qq2, A2.y, v1);
            v1 = fma2(qq3, A3.y, v1);
            v1 = fma2(qq4, A4.y, v1);
            float2 f0 = up(v0), f1 = up(v1);
            acc0 = add2(acc0, pk(ex2(f0.x), ex2(f0.y)));
            acc1 = add2(acc1, pk(ex2(f1.x), ex2(f1.y)));
        }
        float2 a0 = up(acc0), a1 = up(acc1);
        float sum = (a0.x + a0.y) + (a1.x + a1.y);

        float k0 = ((const float*)(sbuf))[n];
        float k1 = ((const float*)(sbuf + 8000))[n];
        float k2 = ((const float*)(sbuf + 16000))[n];
        float k3 = ((const float*)(sbuf + 24000))[n];
        float k4 = ((const float*)(sbuf + 32000))[n];
        float vn = fmaf(q[0], k0, fmaf(q[1], k1,
                   fmaf(q[2], k2, fmaf(q[3], k3, q[4] * k4)))) - shift;
        g_diag[b * NN + n] = ex2(vn) / sum;
    }

    // ---- arrival: last block of batch b runs selection ----
    __threadfence();
    __syncthreads();
    if (t == 0) {
        unsigned old = atomicAdd(&g_cnt[b], 1u);
        s_last = ((old & 7u) == 7u) ? 1 : 0;
    }
    __syncthreads();
    if (!s_last) return;
    __threadfence();

    // ================= selection (one block per batch) ====================
    const float* db = g_diag + b * NN;

    // group sums + argmax (first-max tie-break)
    {
        float bv = -1e30f; int gi = 1 << 30;
        for (int g = t; g < NN / GRP; g += TPB) {
            const float* d5 = db + g * GRP;
            float s = d5[0] + d5[1] + d5[2] + d5[3] + d5[4];
            if (s > bv) { bv = s; gi = g; }
        }
#pragma unroll
        for (int o = 16; o; o >>= 1) {
            float ov = __shfl_xor_sync(0xffffffffu, bv, o);
            int   oi = __shfl_xor_sync(0xffffffffu, gi, o);
            if (ov > bv || (ov == bv && oi < gi)) { bv = ov; gi = oi; }
        }
        if ((t & 31) == 0) { redf[t >> 5] = bv; redi[t >> 5] = gi; }
        __syncthreads();
        if (t == 0) {
            float v = redf[0]; int gi2 = redi[0];
#pragma unroll
            for (int i = 1; i < 8; i++)
                if (redf[i] > v || (redf[i] == v && redi[i] < gi2)) { v = redf[i]; gi2 = redi[i]; }
            const float* gp = base_in + gi2 * GRP * 3;
            float cx = 0.f, cy = 0.f, cz = 0.f;
#pragma unroll
            for (int p = 0; p < GRP; p++) {
                cx += gp[p * 3 + 0]; cy += gp[p * 3 + 1]; cz += gp[p * 3 + 2];
            }
            cen[0] = cx * 0.2f; cen[1] = cy * 0.2f; cen[2] = cz * 0.2f;
        }
        __syncthreads();
    }

    // distances -> keys, with min/max reduction
    u64* key = (u64*)sbuf;
    int* hist = (int*)(sbuf + 16000);
    u64* cand = (u64*)(sbuf + 18048);
    {
        float cx = cen[0], cy = cen[1], cz = cen[2];
        float dmin = 1e30f, dmax = 0.0f;
        for (int m = t; m < NN; m += TPB) {
            const float* p = base_in + m * 3;
            float dx = p[0] - cx, dy = p[1] - cy, dz = p[2] - cz;
            float d = sqrtf(fmaf(dx, dx, fmaf(dy, dy, dz * dz)));
            key[m] = (((u64)__float_as_uint(d)) << 11) | (unsigned)m;
            dmin = fminf(dmin, d); dmax = fmaxf(dmax, d);
        }
#pragma unroll
        for (int o = 16; o; o >>= 1) {
            dmin = fminf(dmin, __shfl_xor_sync(0xffffffffu, dmin, o));
            dmax = fmaxf(dmax, __shfl_xor_sync(0xffffffffu, dmax, o));
        }
        if ((t & 31) == 0) { redf[t >> 5] = dmin; redf2[t >> 5] = dmax; }
        __syncthreads();
        if (t == 0) {
            float mn = redf[0], mx = redf2[0];
#pragma unroll
            for (int i = 1; i < 8; i++) { mn = fminf(mn, redf[i]); mx = fmaxf(mx, redf2[i]); }
            s_dmin = mn; s_dmax = mx;
        }
    }

    // histogram
    for (int i = t; i < 512; i += TPB) hist[i] = 0;
    if (t == 0) s_ncand = 0;
    __syncthreads();
    float dmin = s_dmin, dmax = s_dmax;
    float scale = (dmax > dmin) ? 511.0f / (dmax - dmin) : 0.0f;
    for (int m = t; m < NN; m += TPB) {
        float d = __uint_as_float((unsigned)(key[m] >> 11));
        int bin = min((int)((d - dmin) * scale), 511);
        atomicAdd(&hist[bin], 1);
    }
    __syncthreads();
    if (t == 0) {
        int cum = 0, bs = 511;
        for (int i = 0; i < 512; i++) { cum += hist[i]; if (cum >= TOPK) { bs = i; break; } }
        s_bstar = bs;
    }
    __syncthreads();
    int bs = s_bstar;

    // compact candidates (bin <= bs). Values in higher bins are strictly larger
    // (binning is value-monotone; equal values share a bin), so candidate rank
    // among candidates == global rank.
    for (int m = t; m < NN; m += TPB) {
        u64 kk = key[m];
        float d = __uint_as_float((unsigned)(kk >> 11));
        int bin = min((int)((d - dmin) * scale), 511);
        if (bin <= bs) { int pos = atomicAdd(&s_ncand, 1); cand[pos] = kk; }
    }
    __syncthreads();
    int nc = s_ncand;

    // exact stable rank among candidates; emit top-110
    for (int ci = t; ci < nc; ci += TPB) {
        u64 kn = cand[ci];
        int r = 0;
        for (int j = 0; j < nc; j++) r += (int)(cand[j] < kn);
        if (r < TOPK) {
            int m = (int)(kn & 2047u);
            const float* p = base_in + m * 3;
            float* o = out + (b * TOPK + r) * 3;
            o[0] = p[0]; o[1] = p[1]; o[2] = p[2];
        }
    }
}

// ---------------------------------------------------------------------------
extern "C" void kernel_launch(void* const* d_in, const int* in_sizes, int n_in,
                              void* d_out, int out_size) {
    const float* in_mat = (const float*)d_in[0];
    const float* Wi = (const float*)d_in[1];
    const float* bi = (const float*)d_in[2];
    const float* Wq = (const float*)d_in[3];
    const float* bq = (const float*)d_in[4];
    const float* Wk = (const float*)d_in[5];
    const float* bk = (const float*)d_in[6];
    // d_in[7..10] (Wv,bv,Wo,bo) are dead w.r.t. the output.
    float* out = (float*)d_out;

    fused_kernel<<<dim3(NCHUNK, BB), TPB>>>(in_mat, Wi, bi, Wq, bq, Wk, bk, out);
}

// round 6
// speedup vs baseline: 7.8178x; 1.4394x over previous
#include <cuda_runtime.h>

#define BB 32
#define NN 2000
#define DD 5
#define GRP 5
#define TOPK 110
#define TPB 256
#define NCHUNK 9
#define CHUNK 223

typedef unsigned long long u64;

__device__ float g_diag[BB * NN];
__device__ unsigned int g_cnt[BB];   // monotonic; each launch adds exactly NCHUNK per batch

// ---- PTX helpers ----------------------------------------------------------
__device__ __forceinline__ float ex2(float x) {
    float y; asm("ex2.approx.ftz.f32 %0, %1;" : "=f"(y) : "f"(x)); return y;
}
__device__ __forceinline__ u64 pk(float lo, float hi) {
    u64 r; asm("mov.b64 %0, {%1, %2};" : "=l"(r) : "f"(lo), "f"(hi)); return r;
}
__device__ __forceinline__ float2 up(u64 v) {
    float2 r; asm("mov.b64 {%0, %1}, %2;" : "=f"(r.x), "=f"(r.y) : "l"(v)); return r;
}
__device__ __forceinline__ u64 fma2(u64 a, u64 b, u64 c) {
    u64 d; asm("fma.rn.f32x2 %0, %1, %2, %3;" : "=l"(d) : "l"(a), "l"(b), "l"(c)); return d;
}
__device__ __forceinline__ u64 add2(u64 a, u64 b) {
    u64 d; asm("add.rn.f32x2 %0, %1, %2;" : "=l"(d) : "l"(a), "l"(b)); return d;
}

// ---------------------------------------------------------------------------
// Fused kernel. grid = (9, 32), block = 256.
// score(n,m)*log2e = alpha_n . in[m] + const_n  (const cancels in softmax),
// where alpha_n = (log2e/sqrt(5)) * Wi (Wk q_n)  -- 3-dim!
//
// smem sbuf (34048 B):
//   diag phase : P0 f32[2000] @0, P1 @8000, P2 @16000  (transposed in_mat[b])
//   select phase (overlay, last-arriving block only):
//     key u64[2000] @0, hist int[512] @16000, cand u64[2000] @18048
// ---------------------------------------------------------------------------
__global__ void __launch_bounds__(TPB, 2) fused_kernel(
    const float* __restrict__ in_mat,
    const float* __restrict__ Wi, const float* __restrict__ bi,
    const float* __restrict__ Wq, const float* __restrict__ bq,
    const float* __restrict__ Wk,
    float* __restrict__ out)
{
    __shared__ __align__(16) char sbuf[34048];
    __shared__ float wsm[75];   // 0:Wi(15) 15:bi(5) 20:Wq(25) 45:bq(5) 50:Wk(25)
    __shared__ float redf[8];
    __shared__ float redf2[8];
    __shared__ int   redi[8];
    __shared__ float cen[3];
    __shared__ int s_ncand, s_bstar, s_last;
    __shared__ float s_dmin, s_dmax;

    const int b = blockIdx.y, c = blockIdx.x, t = threadIdx.x;
    const float* base_in = in_mat + b * NN * 3;

    float* P0 = (float*)(sbuf);
    float* P1 = (float*)(sbuf + 8000);
    float* P2 = (float*)(sbuf + 16000);

    // ---- stage weights ----
    if (t < 15)      wsm[t] = Wi[t];
    else if (t < 20) wsm[t] = bi[t - 15];
    else if (t < 45) wsm[t] = Wq[t - 20];
    else if (t < 50) wsm[t] = bq[t - 45];
    else if (t < 75) wsm[t] = Wk[t - 50];
    __syncthreads();

    // ---- phase 1: transpose in_mat[b] -> SoA smem, track max ||in||^2 ----
    float bmax = 0.0f;
    for (int p = t; p < NN; p += TPB) {
        float i0 = base_in[p * 3], i1 = base_in[p * 3 + 1], i2 = base_in[p * 3 + 2];
        P0[p] = i0; P1[p] = i1; P2[p] = i2;
        bmax = fmaxf(bmax, fmaf(i0, i0, fmaf(i1, i1, i2 * i2)));
    }
#pragma unroll
    for (int o = 16; o; o >>= 1) bmax = fmaxf(bmax, __shfl_xor_sync(0xffffffffu, bmax, o));
    if ((t & 31) == 0) redf[t >> 5] = bmax;
    __syncthreads();
    float maxn2 = redf[0];
#pragma unroll
    for (int i = 1; i < 8; i++) maxn2 = fmaxf(maxn2, redf[i]);

    // ---- phase 2: alpha_n, then branchless diag softmax over raw inputs ----
    const int n = c * CHUNK + t;
    if (t < CHUNK && n < NN) {
        float i0 = base_in[n * 3], i1 = base_in[n * 3 + 1], i2 = base_in[n * 3 + 2];
        float x[DD];
#pragma unroll
        for (int j = 0; j < DD; j++)
            x[j] = fmaf(i0, wsm[j], fmaf(i1, wsm[5 + j], fmaf(i2, wsm[10 + j], wsm[15 + j])));
        float q[DD];
#pragma unroll
        for (int j = 0; j < DD; j++) {
            float qq = wsm[45 + j];
#pragma unroll
            for (int d = 0; d < DD; d++) qq = fmaf(x[d], wsm[20 + d * 5 + j], qq);
            q[j] = qq;
        }
        // wkq_d = sum_j Wk[d][j] * q[j]
        float wkq[DD];
#pragma unroll
        for (int d = 0; d < DD; d++) {
            float s = 0.f;
#pragma unroll
            for (int j = 0; j < DD; j++) s = fmaf(wsm[50 + d * 5 + j], q[j], s);
            wkq[d] = s;
        }
        const float qscale = 1.4426950408889634f / 2.2360679774997896f; // log2e/sqrt(5)
        float a0 = 0.f, a1 = 0.f, a2 = 0.f;
#pragma unroll
        for (int d = 0; d < DD; d++) {
            a0 = fmaf(wsm[0 + d], wkq[d], a0);
            a1 = fmaf(wsm[5 + d], wkq[d], a1);
            a2 = fmaf(wsm[10 + d], wkq[d], a2);
        }
        a0 *= qscale; a1 *= qscale; a2 *= qscale;

        // shift >= max_m alpha . in[m]  (Cauchy-Schwarz; softmax shift-invariant)
        float shift = sqrtf(fmaf(a0, a0, fmaf(a1, a1, a2 * a2))) * sqrtf(maxn2);

        u64 ax = pk(a0, a0), ay = pk(a1, a1), az = pk(a2, a2);
        u64 ns = pk(-shift, -shift);

        const ulonglong2* Q0 = (const ulonglong2*)P0;
        const ulonglong2* Q1 = (const ulonglong2*)P1;
        const ulonglong2* Q2 = (const ulonglong2*)P2;

        u64 acc0 = 0ull, acc1 = 0ull;
#pragma unroll 4
        for (int p = 0; p < NN / 4; p++) {
            ulonglong2 A0 = Q0[p], A1 = Q1[p], A2 = Q2[p];
            u64 v0 = fma2(ax, A0.x, ns);
            v0 = fma2(ay, A1.x, v0);
            v0 = fma2(az, A2.x, v0);
            u64 v1 = fma2(ax, A0.y, ns);
            v1 = fma2(ay, A1.y, v1);
            v1 = fma2(az, A2.y, v1);
            float2 f0 = up(v0), f1 = up(v1);
            acc0 = add2(acc0, pk(ex2(f0.x), ex2(f0.y)));
            acc1 = add2(acc1, pk(ex2(f1.x), ex2(f1.y)));
        }
        float2 s0 = up(acc0), s1 = up(acc1);
        float sum = (s0.x + s0.y) + (s1.x + s1.y);

        float vn = fmaf(a0, i0, fmaf(a1, i1, a2 * i2)) - shift;
        g_diag[b * NN + n] = ex2(vn) / sum;
    }

    // ---- arrival: last block of batch b runs selection ----
    __threadfence();
    __syncthreads();
    if (t == 0) {
        unsigned old = atomicAdd(&g_cnt[b], 1u);
        s_last = ((old % NCHUNK) == NCHUNK - 1) ? 1 : 0;
    }
    __syncthreads();
    if (!s_last) return;
    __threadfence();

    // ================= selection (one block per batch) ====================
    const float* db = g_diag + b * NN;

    // group sums + argmax (first-max tie-break == jnp.argmax)
    {
        float bv = -1e30f; int gi = 1 << 30;
        for (int g = t; g < NN / GRP; g += TPB) {
            const float* d5 = db + g * GRP;
            float s = d5[0] + d5[1] + d5[2] + d5[3] + d5[4];
            if (s > bv) { bv = s; gi = g; }
        }
#pragma unroll
        for (int o = 16; o; o >>= 1) {
            float ov = __shfl_xor_sync(0xffffffffu, bv, o);
            int   oi = __shfl_xor_sync(0xffffffffu, gi, o);
            if (ov > bv || (ov == bv && oi < gi)) { bv = ov; gi = oi; }
        }
        if ((t & 31) == 0) { redf[t >> 5] = bv; redi[t >> 5] = gi; }
        __syncthreads();
        if (t == 0) {
            float v = redf[0]; int gi2 = redi[0];
#pragma unroll
            for (int i = 1; i < 8; i++)
                if (redf[i] > v || (redf[i] == v && redi[i] < gi2)) { v = redf[i]; gi2 = redi[i]; }
            const float* gp = base_in + gi2 * GRP * 3;
            float cx = 0.f, cy = 0.f, cz = 0.f;
#pragma unroll
            for (int p = 0; p < GRP; p++) {
                cx += gp[p * 3 + 0]; cy += gp[p * 3 + 1]; cz += gp[p * 3 + 2];
            }
            cen[0] = cx * 0.2f; cen[1] = cy * 0.2f; cen[2] = cz * 0.2f;
        }
        __syncthreads();
    }

    u64* key  = (u64*)sbuf;
    int* hist = (int*)(sbuf + 16000);
    u64* cand = (u64*)(sbuf + 18048);

    // distances -> keys, min/max reduction
    {
        float cx = cen[0], cy = cen[1], cz = cen[2];
        float dmin = 1e30f, dmax = 0.0f;
        for (int m = t; m < NN; m += TPB) {
            const float* p = base_in + m * 3;
            float dx = p[0] - cx, dy = p[1] - cy, dz = p[2] - cz;
            float d = sqrtf(fmaf(dx, dx, fmaf(dy, dy, dz * dz)));
            key[m] = (((u64)__float_as_uint(d)) << 11) | (unsigned)m;
            dmin = fminf(dmin, d); dmax = fmaxf(dmax, d);
        }
#pragma unroll
        for (int o = 16; o; o >>= 1) {
            dmin = fminf(dmin, __shfl_xor_sync(0xffffffffu, dmin, o));
            dmax = fmaxf(dmax, __shfl_xor_sync(0xffffffffu, dmax, o));
        }
        if ((t & 31) == 0) { redf[t >> 5] = dmin; redf2[t >> 5] = dmax; }
        __syncthreads();
        if (t == 0) {
            float mn = redf[0], mx = redf2[0];
#pragma unroll
            for (int i = 1; i < 8; i++) { mn = fminf(mn, redf[i]); mx = fmaxf(mx, redf2[i]); }
            s_dmin = mn; s_dmax = mx;
        }
    }

    for (int i = t; i < 512; i += TPB) hist[i] = 0;
    if (t == 0) s_ncand = 0;
    __syncthreads();
    float dmin = s_dmin, dmax = s_dmax;
    float scale = (dmax > dmin) ? 511.0f / (dmax - dmin) : 0.0f;
    for (int m = t; m < NN; m += TPB) {
        float d = __uint_as_float((unsigned)(key[m] >> 11));
        int bin = min((int)((d - dmin) * scale), 511);
        atomicAdd(&hist[bin], 1);
    }
    __syncthreads();
    if (t == 0) {
        int cum = 0, bs = 511;
        for (int i = 0; i < 512; i++) { cum += hist[i]; if (cum >= TOPK) { bs = i; break; } }
        s_bstar = bs;
    }
    __syncthreads();
    int bs = s_bstar;

    // compact candidates (bin <= bs): binning is value-monotone, so candidate
    // rank among candidates == global rank.
    for (int m = t; m < NN; m += TPB) {
        u64 kk = key[m];
        float d = __uint_as_float((unsigned)(kk >> 11));
        int bin = min((int)((d - dmin) * scale), 511);
        if (bin <= bs) { int pos = atomicAdd(&s_ncand, 1); cand[pos] = kk; }
    }
    __syncthreads();
    int nc = s_ncand;

    // exact stable rank among candidates (== jax.lax.top_k order); emit top-110
    for (int ci = t; ci < nc; ci += TPB) {
        u64 kn = cand[ci];
        int r = 0;
        for (int j = 0; j < nc; j++) r += (int)(cand[j] < kn);
        if (r < TOPK) {
            int m = (int)(kn & 2047u);
            const float* p = base_in + m * 3;
            float* o = out + (b * TOPK + r) * 3;
            o[0] = p[0]; o[1] = p[1]; o[2] = p[2];
        }
    }
}

// ---------------------------------------------------------------------------
extern "C" void kernel_launch(void* const* d_in, const int* in_sizes, int n_in,
                              void* d_out, int out_size) {
    const float* in_mat = (const float*)d_in[0];
    const float* Wi = (const float*)d_in[1];
    const float* bi = (const float*)d_in[2];
    const float* Wq = (const float*)d_in[3];
    const float* bq = (const float*)d_in[4];
    const float* Wk = (const float*)d_in[5];
    // bk (d_in[6]) cancels in softmax; d_in[7..10] (Wv,bv,Wo,bo) are dead.
    float* out = (float*)d_out;

    fused_kernel<<<dim3(NCHUNK, BB), TPB>>>(in_mat, Wi, bi, Wq, bq, Wk, out);
}